// round 1
// baseline (speedup 1.0000x reference)
#include <cuda_runtime.h>

#define Bn 8
#define Cn 24
#define Mn 960
#define Wn 15                 // 64-bit words per row (960/64)
#define ROWS (Bn*Mn)          // 7680
#define NW (ROWS*Wn)          // 115200 words total

// Scratch bitmaps (device globals — no allocation allowed)
__device__ unsigned long long g_frontier[NW];
__device__ unsigned long long g_H[6][NW];   // r = 4,6,7,8,9,10
__device__ unsigned long long g_eroded[NW];

// K1: pack frontier = (channel-1 == 0) into bitmaps via warp ballot.
__global__ void pack_kernel(const float* __restrict__ in) {
    int p = blockIdx.x * blockDim.x + threadIdx.x;   // pixel id, exact grid
    int b = p / (Mn * Mn);
    int rem = p - b * (Mn * Mn);
    float v = in[(size_t)(b * Cn + 1) * (Mn * Mn) + rem];
    unsigned mask = __ballot_sync(0xffffffffu, v == 0.0f);
    if ((p & 31) == 0)
        ((unsigned*)g_frontier)[p >> 5] = mask;
}

// K2: horizontal erosions. One thread per 64-bit word; incremental window AND.
__global__ void hrode_kernel() {
    int i = blockIdx.x * blockDim.x + threadIdx.x;
    if (i >= NW) return;
    int w = i % Wn;
    unsigned long long c = g_frontier[i];
    unsigned long long l = (w > 0)      ? g_frontier[i - 1] : 0ULL;
    unsigned long long r = (w < Wn - 1) ? g_frontier[i + 1] : 0ULL;
    unsigned long long acc = c;
#pragma unroll
    for (int d = 1; d <= 10; d++) {
        acc &= ((c << d) | (l >> (64 - d))) & ((c >> d) | (r << (64 - d)));
        if (d == 4)       g_H[0][i] = acc;
        else if (d == 6)  g_H[1][i] = acc;
        else if (d == 7)  g_H[2][i] = acc;
        else if (d == 8)  g_H[3][i] = acc;
        else if (d == 9)  g_H[4][i] = acc;
        else if (d == 10) g_H[5][i] = acc;
    }
}

// K3: vertical combine — AND the 21 row-offset terms of the disk.
__global__ void verode_kernel() {
    int i = blockIdx.x * blockDim.x + threadIdx.x;
    if (i >= NW) return;
    int y = (i / Wn) % Mn;
    unsigned long long e = 0ULL;
    if (y >= 10 && y <= Mn - 11) {
        e  = g_H[5][i];                                        // dy=0,  r=10
        e &= g_H[4][i - 1*Wn]  & g_H[4][i + 1*Wn];             // |dy|=1, r=9
        e &= g_H[4][i - 2*Wn]  & g_H[4][i + 2*Wn];             // |dy|=2, r=9
        e &= g_H[4][i - 3*Wn]  & g_H[4][i + 3*Wn];             // |dy|=3, r=9
        e &= g_H[4][i - 4*Wn]  & g_H[4][i + 4*Wn];             // |dy|=4, r=9
        e &= g_H[3][i - 5*Wn]  & g_H[3][i + 5*Wn];             // |dy|=5, r=8
        e &= g_H[3][i - 6*Wn]  & g_H[3][i + 6*Wn];             // |dy|=6, r=8
        e &= g_H[2][i - 7*Wn]  & g_H[2][i + 7*Wn];             // |dy|=7, r=7
        e &= g_H[1][i - 8*Wn]  & g_H[1][i + 8*Wn];             // |dy|=8, r=6
        e &= g_H[0][i - 9*Wn]  & g_H[0][i + 9*Wn];             // |dy|=9, r=4
        e &= g_frontier[i - 10*Wn] & g_frontier[i + 10*Wn];    // |dy|=10, r=0
    }
    g_eroded[i] = e;
}

// K4: border = dilate(eroded, cross) & ~eroded, expanded to float output.
__global__ void border_kernel(float* __restrict__ out) {
    int p = blockIdx.x * blockDim.x + threadIdx.x;   // pixel id
    int x = p % Mn;
    int row = p / Mn;                                 // b*M + y
    int y = row % Mn;
    int w = x >> 6, li = x & 63;
    int base = row * Wn + w;
    unsigned long long e  = g_eroded[base];
    unsigned long long eu = (y > 0)      ? g_eroded[base - Wn] : 0ULL;
    unsigned long long ed = (y < Mn - 1) ? g_eroded[base + Wn] : 0ULL;
    unsigned bc = (unsigned)(e >> li) & 1u;
    unsigned d  = bc | ((unsigned)(eu >> li) & 1u) | ((unsigned)(ed >> li) & 1u);
    unsigned bl, br;
    if (li > 0) bl = (unsigned)(e >> (li - 1)) & 1u;
    else        bl = (w > 0) ? (unsigned)(g_eroded[base - 1] >> 63) & 1u : 0u;
    if (li < 63) br = (unsigned)(e >> (li + 1)) & 1u;
    else         br = (w < Wn - 1) ? (unsigned)g_eroded[base + 1] & 1u : 0u;
    d |= bl | br;
    out[p] = (float)(d & (bc ^ 1u));
}

extern "C" void kernel_launch(void* const* d_in, const int* in_sizes, int n_in,
                              void* d_out, int out_size) {
    const float* map_features = (const float*)d_in[0];
    float* out = (float*)d_out;

    const int npix = Bn * Mn * Mn;               // 7,372,800
    pack_kernel<<<npix / 256, 256>>>(map_features);
    hrode_kernel<<<(NW + 127) / 128, 128>>>();
    verode_kernel<<<(NW + 127) / 128, 128>>>();
    border_kernel<<<npix / 256, 256>>>(out);
}

// round 2
// speedup vs baseline: 2.2973x; 2.2973x over previous
#include <cuda_runtime.h>

#define Bn 8
#define Cn 24
#define Mn 960
#define Wn 15                 // 64-bit words per row (960/64)
#define ROWS (Bn*Mn)          // 7680
#define NW (ROWS*Wn)          // 115200 words total

// Scratch bitmaps (device globals — no allocation allowed)
__device__ unsigned long long g_frontier[NW];
__device__ unsigned long long g_H[6][NW];   // r = 4,6,7,8,9,10
__device__ unsigned long long g_eroded[NW];

// K1: pack frontier = (channel-1 == 0). Warp handles 128 consecutive pixels:
// 4 strided coalesced loads + 4 ballots + one uint4 store from lane 0.
__global__ void pack_kernel(const float* __restrict__ in) {
    int warp = (blockIdx.x * blockDim.x + threadIdx.x) >> 5;
    int lane = threadIdx.x & 31;
    int pbase = warp << 7;                       // 128 px per warp, never spans batch
    int b = pbase / (Mn * Mn);
    int rem = pbase - b * (Mn * Mn);
    const float* src = in + (size_t)(b * Cn + 1) * (Mn * Mn) + rem + lane;
    unsigned r0 = __ballot_sync(0xffffffffu, src[0]  == 0.0f);
    unsigned r1 = __ballot_sync(0xffffffffu, src[32] == 0.0f);
    unsigned r2 = __ballot_sync(0xffffffffu, src[64] == 0.0f);
    unsigned r3 = __ballot_sync(0xffffffffu, src[96] == 0.0f);
    if (lane == 0)
        ((uint4*)g_frontier)[warp] = make_uint4(r0, r1, r2, r3);
}

// K2: horizontal erosions. One thread per 64-bit word; incremental window AND.
__global__ void hrode_kernel() {
    int i = blockIdx.x * blockDim.x + threadIdx.x;
    if (i >= NW) return;
    int w = i % Wn;
    unsigned long long c = g_frontier[i];
    unsigned long long l = (w > 0)      ? g_frontier[i - 1] : 0ULL;
    unsigned long long r = (w < Wn - 1) ? g_frontier[i + 1] : 0ULL;
    unsigned long long acc = c;
#pragma unroll
    for (int d = 1; d <= 10; d++) {
        acc &= ((c << d) | (l >> (64 - d))) & ((c >> d) | (r << (64 - d)));
        if (d == 4)       g_H[0][i] = acc;
        else if (d == 6)  g_H[1][i] = acc;
        else if (d == 7)  g_H[2][i] = acc;
        else if (d == 8)  g_H[3][i] = acc;
        else if (d == 9)  g_H[4][i] = acc;
        else if (d == 10) g_H[5][i] = acc;
    }
}

// K3: vertical combine — AND the 21 row-offset terms of the disk.
__global__ void verode_kernel() {
    int i = blockIdx.x * blockDim.x + threadIdx.x;
    if (i >= NW) return;
    int y = (i / Wn) % Mn;
    unsigned long long e = 0ULL;
    if (y >= 10 && y <= Mn - 11) {
        e  = g_H[5][i];                                        // dy=0,  r=10
        e &= g_H[4][i - 1*Wn]  & g_H[4][i + 1*Wn];             // |dy|=1, r=9
        e &= g_H[4][i - 2*Wn]  & g_H[4][i + 2*Wn];             // |dy|=2, r=9
        e &= g_H[4][i - 3*Wn]  & g_H[4][i + 3*Wn];             // |dy|=3, r=9
        e &= g_H[4][i - 4*Wn]  & g_H[4][i + 4*Wn];             // |dy|=4, r=9
        e &= g_H[3][i - 5*Wn]  & g_H[3][i + 5*Wn];             // |dy|=5, r=8
        e &= g_H[3][i - 6*Wn]  & g_H[3][i + 6*Wn];             // |dy|=6, r=8
        e &= g_H[2][i - 7*Wn]  & g_H[2][i + 7*Wn];             // |dy|=7, r=7
        e &= g_H[1][i - 8*Wn]  & g_H[1][i + 8*Wn];             // |dy|=8, r=6
        e &= g_H[0][i - 9*Wn]  & g_H[0][i + 9*Wn];             // |dy|=9, r=4
        e &= g_frontier[i - 10*Wn] & g_frontier[i + 10*Wn];    // |dy|=10, r=0
    }
    g_eroded[i] = e;
}

// K4: border = dilate(eroded, cross) & ~eroded, word-parallel, then nibble->float4
// LUT expansion with fully coalesced float4 stores.
#define RB 16                  // rows per block (960 % 16 == 0, never spans batch)
#define TW (RB*Wn)             // 240 words per block
__global__ void border_kernel(float* __restrict__ out) {
    __shared__ unsigned long long sb[TW];
    __shared__ float4 lut[16];
    int t = threadIdx.x;
    if (t < 16)
        lut[t] = make_float4(t & 1 ? 1.0f : 0.0f, t & 2 ? 1.0f : 0.0f,
                             t & 4 ? 1.0f : 0.0f, t & 8 ? 1.0f : 0.0f);
    int row0 = blockIdx.x * RB;                  // global row (b*Mn + y)
    if (t < TW) {
        int rr = t / Wn, w = t - rr * Wn;
        int row = row0 + rr;
        int y = row % Mn;
        int i = row * Wn + w;
        unsigned long long e  = g_eroded[i];
        unsigned long long eu = (y > 0)      ? g_eroded[i - Wn] : 0ULL;
        unsigned long long ed = (y < Mn - 1) ? g_eroded[i + Wn] : 0ULL;
        unsigned long long l  = (w > 0)      ? g_eroded[i - 1]  : 0ULL;
        unsigned long long r  = (w < Wn - 1) ? g_eroded[i + 1]  : 0ULL;
        unsigned long long d = e | eu | ed | (e << 1) | (l >> 63) | (e >> 1) | (r << 63);
        sb[t] = d & ~e;
    }
    __syncthreads();
    float4* o = (float4*)out + (size_t)row0 * (Mn / 4);
#pragma unroll
    for (int k = 0; k < (TW * 16) / 256; k++) {  // 15 iterations, exact
        int c = t + k * 256;                     // float4 chunk within tile
        unsigned long long bw = sb[c >> 4];
        unsigned nib = (unsigned)(bw >> ((c & 15) << 2)) & 15u;
        o[c] = lut[nib];
    }
}

extern "C" void kernel_launch(void* const* d_in, const int* in_sizes, int n_in,
                              void* d_out, int out_size) {
    const float* map_features = (const float*)d_in[0];
    float* out = (float*)d_out;

    const int npix = Bn * Mn * Mn;               // 7,372,800
    pack_kernel<<<npix / (128 * 8), 256>>>(map_features);   // 8 warps/block
    hrode_kernel<<<(NW + 255) / 256, 256>>>();
    verode_kernel<<<(NW + 255) / 256, 256>>>();
    border_kernel<<<ROWS / RB, 256>>>(out);
}

// round 3
// speedup vs baseline: 2.5373x; 1.1045x over previous
#include <cuda_runtime.h>

#define Bn 8
#define Cn 24
#define Mn 960
#define Wn 15                  // 64-bit words per row (960/64)
#define ROWS (Bn*Mn)           // 7680
#define NW (ROWS*Wn)           // 115200 words total

#define RB 16                  // output rows per block (960 % 16 == 0)
#define RT (RB + 22)           // hrode rows needed (halo ±11) = 38
#define PW 17                  // padded words per smem row (bank de-phase)

// Scratch bitmap (device global — no allocation allowed)
__device__ unsigned long long g_frontier[NW];

// K1: pack frontier = (channel-1 == 0). Warp handles 128 consecutive pixels:
// 4 strided coalesced loads + 4 ballots + one uint4 store from lane 0.
__global__ void pack_kernel(const float* __restrict__ in) {
    int warp = (blockIdx.x * blockDim.x + threadIdx.x) >> 5;
    int lane = threadIdx.x & 31;
    int pbase = warp << 7;                        // 128 px per warp, never spans batch
    int b = pbase / (Mn * Mn);
    int rem = pbase - b * (Mn * Mn);
    const float* src = in + (size_t)(b * Cn + 1) * (Mn * Mn) + rem + lane;
    unsigned r0 = __ballot_sync(0xffffffffu, src[0]  == 0.0f);
    unsigned r1 = __ballot_sync(0xffffffffu, src[32] == 0.0f);
    unsigned r2 = __ballot_sync(0xffffffffu, src[64] == 0.0f);
    unsigned r3 = __ballot_sync(0xffffffffu, src[96] == 0.0f);
    if (lane == 0)
        ((uint4*)g_frontier)[warp] = make_uint4(r0, r1, r2, r3);
}

// K2: fully fused morphology — hrode (in-smem, halo recompute), verode,
// cross-border, and nibble->float4 expansion with coalesced stores.
__global__ void __launch_bounds__(256) morph_kernel(float* __restrict__ out) {
    __shared__ unsigned long long sF[RT][PW];      // frontier rows (r=0 term)
    __shared__ unsigned long long sH[6][RT][PW];   // r = 4,6,7,8,9,10
    __shared__ unsigned long long sE[RB + 2][PW];  // eroded rows (±1 halo)
    __shared__ unsigned long long sB[RB][PW];      // border words

    const int t  = threadIdx.x;
    const int r0 = blockIdx.x * RB;                // global row base
    const int b  = r0 / Mn;
    const int y0 = r0 - b * Mn;                    // image-local row base

    // Phase A: horizontal erosions for rows y0-11 .. y0+RB+10
    for (int task = t; task < RT * Wn; task += 256) {
        int rr = task / Wn, w = task - rr * Wn;
        int y = y0 + rr - 11;
        unsigned long long c = 0, l = 0, r = 0;
        if (y >= 0 && y < Mn) {
            int i = (b * Mn + y) * Wn + w;
            c = g_frontier[i];
            l = (w > 0)      ? g_frontier[i - 1] : 0ULL;
            r = (w < Wn - 1) ? g_frontier[i + 1] : 0ULL;
        }
        sF[rr][w] = c;
        unsigned long long acc = c;
#pragma unroll
        for (int d = 1; d <= 10; d++) {
            acc &= ((c << d) | (l >> (64 - d))) & ((c >> d) | (r << (64 - d)));
            if (d == 4)       sH[0][rr][w] = acc;
            else if (d == 6)  sH[1][rr][w] = acc;
            else if (d == 7)  sH[2][rr][w] = acc;
            else if (d == 8)  sH[3][rr][w] = acc;
            else if (d == 9)  sH[4][rr][w] = acc;
            else if (d == 10) sH[5][rr][w] = acc;
        }
    }
    __syncthreads();

    // Phase B: vertical AND of 21 disk terms -> eroded rows y0-1 .. y0+RB
    for (int task = t; task < (RB + 2) * Wn; task += 256) {
        int rr = task / Wn, w = task - rr * Wn;
        int y = y0 + rr - 1;
        unsigned long long e = 0ULL;
        if (y >= 10 && y <= Mn - 11) {
            int h = rr + 10;                       // hrode smem row of dy=0
            e  = sH[5][h][w];
            e &= sH[4][h - 1][w] & sH[4][h + 1][w];
            e &= sH[4][h - 2][w] & sH[4][h + 2][w];
            e &= sH[4][h - 3][w] & sH[4][h + 3][w];
            e &= sH[4][h - 4][w] & sH[4][h + 4][w];
            e &= sH[3][h - 5][w] & sH[3][h + 5][w];
            e &= sH[3][h - 6][w] & sH[3][h + 6][w];
            e &= sH[2][h - 7][w] & sH[2][h + 7][w];
            e &= sH[1][h - 8][w] & sH[1][h + 8][w];
            e &= sH[0][h - 9][w] & sH[0][h + 9][w];
            e &= sF[h - 10][w]   & sF[h + 10][w];
        }
        sE[rr][w] = e;
    }
    __syncthreads();

    // Phase C: cross-dilation border = dilate(e) & ~e, word-parallel
    for (int task = t; task < RB * Wn; task += 256) {
        int rr = task / Wn, w = task - rr * Wn;
        unsigned long long e  = sE[rr + 1][w];
        unsigned long long eu = sE[rr][w];
        unsigned long long ed = sE[rr + 2][w];
        unsigned long long l  = (w > 0)      ? sE[rr + 1][w - 1] : 0ULL;
        unsigned long long r  = (w < Wn - 1) ? sE[rr + 1][w + 1] : 0ULL;
        unsigned long long d = e | eu | ed | (e << 1) | (l >> 63) | (e >> 1) | (r << 63);
        sB[rr][w] = d & ~e;
    }
    __syncthreads();

    // Phase D: expand bits -> float4, fully coalesced stores
    float4* o = (float4*)out + (size_t)r0 * (Mn / 4);
#pragma unroll
    for (int k = 0; k < (RB * (Mn / 4)) / 256; k++) {   // 15 iterations, exact
        int c = t + (k << 8);                    // float4 chunk in tile
        int rr = c / (Mn / 4), cc = c - rr * (Mn / 4);
        unsigned long long bw = sB[rr][cc >> 4];
        unsigned nib = (unsigned)(bw >> ((cc & 15) << 2)) & 15u;
        o[c] = make_float4(nib & 1u ? 1.0f : 0.0f, nib & 2u ? 1.0f : 0.0f,
                           nib & 4u ? 1.0f : 0.0f, nib & 8u ? 1.0f : 0.0f);
    }
}

extern "C" void kernel_launch(void* const* d_in, const int* in_sizes, int n_in,
                              void* d_out, int out_size) {
    const float* map_features = (const float*)d_in[0];
    float* out = (float*)d_out;

    const int npix = Bn * Mn * Mn;                // 7,372,800
    pack_kernel<<<npix / (128 * 8), 256>>>(map_features);   // 8 warps/block
    morph_kernel<<<ROWS / RB, 256>>>(out);
}